// round 12
// baseline (speedup 1.0000x reference)
#include <cuda_runtime.h>
#include <stdint.h>

// Problem shape (fixed)
#define BB    64
#define TT    128
#define CIN   2048
#define COUT  2048
#define NRB   256          // COUT/8 block-rows
#define NCB   256          // CIN/8  block-cols
#define KCAP  48           // max kept blocks per block-row (validated R11)
#define NTHR  128          // threads per GEMM CTA (4 warps)

#define PACK_BLOCKS 8192   // fused kernel: first 8192 CTAs pack, next 256 prep

#define B_PITCH 528                    // bytes per n-row in smem B
#define C_PITCH 9                      // fp32 words per staged C row
#define BLK_PITCH 1040                 // bytes per expanded block-col in smem (65*16)
#define CHUNK_BYTES (4 * BLK_PITCH)    // 4160 per pipeline stage

// Dynamic smem layout (A stage buffers reused for C staging after mainloop)
#define SAB_OFF   0
#define SAB_BYTES (2 * CHUNK_BYTES)           // 8320 (>= 128*C_PITCH*4 = 4608)
#define SB_OFF    SAB_BYTES
#define SBITS_OFF (SB_OFF + 8 * B_PITCH)      // 12544
#define SMEM_G    (SBITS_OFF + 256)           // 12800 -> ~16 CTAs/SM

// Scratch (static device globals — no runtime allocation)
// g_Aexp[cb][b]: 1KB of expanded 0/1 bytes.  16B unit at pos16(g,mt) =
// g*8 + ((mt + 4*(g&1)) & 7); unit = {row mt*16+g ch0..7, row mt*16+8+g ch0..7}.
__device__ __align__(16) uint8_t g_Aexp[(size_t)NCB * BB * 1024];  // 16MB
__device__ __align__(16) int8_t  g_Bc[(size_t)NRB * 8 * KCAP * 8]; // interleaved k-order
__device__ uint8_t g_cols[NRB * KCAP];
__device__ int     g_nk[NRB];

// ---------------------------------------------------------------------------
// helpers
// ---------------------------------------------------------------------------
__device__ __forceinline__ uint32_t smem_u32(const void* p) {
    uint32_t a;
    asm("{ .reg .u64 t; cvta.to.shared.u64 t, %1; cvt.u32.u64 %0, t; }" : "=r"(a) : "l"(p));
    return a;
}
__device__ __forceinline__ void cp_async16(uint32_t dst, const void* src) {
    asm volatile("cp.async.cg.shared.global [%0], [%1], 16;" :: "r"(dst), "l"(src) : "memory");
}
__device__ __forceinline__ void cp_commit() {
    asm volatile("cp.async.commit_group;" ::: "memory");
}
__device__ __forceinline__ void cp_wait0() {
    asm volatile("cp.async.wait_group 0;" ::: "memory");
}
__device__ __forceinline__ void mma_s8(int* c, uint32_t a0, uint32_t a1, uint32_t a2,
                                       uint32_t a3, uint32_t b0, uint32_t b1) {
    asm volatile(
        "mma.sync.aligned.m16n8k32.row.col.s32.s8.s8.s32 "
        "{%0,%1,%2,%3}, {%4,%5,%6,%7}, {%8,%9}, {%0,%1,%2,%3};"
        : "+r"(c[0]), "+r"(c[1]), "+r"(c[2]), "+r"(c[3])
        : "r"(a0), "r"(a1), "r"(a2), "r"(a3), "r"(b0), "r"(b1));
}

// ---------------------------------------------------------------------------
// Kernel 1 (fused): CTAs [0, PACK_BLOCKS) expand spikes into g_Aexp;
// CTAs [PACK_BLOCKS, +NRB) do the per-block-row weight compaction.
// ---------------------------------------------------------------------------
__global__ void __launch_bounds__(256) pack_prep_kernel(const float* __restrict__ spikes,
                                                        const float* __restrict__ W,
                                                        const float* __restrict__ M) {
    int bid = blockIdx.x;
    int tid = threadIdx.x;

    if (bid < PACK_BLOCKS) {
        // ---- pack: thread = (cb, b, t); emit 8 expanded bytes (uint2) ----
        int b  = bid >> 7;                 // 64 batches
        int cb = (bid & 127) * 2 + (tid >> 7);
        int t  = tid & 127;
        const float* sp = spikes + ((size_t)b * CIN + cb * 8) * TT + t;
        uint32_t u0 = 0, u1 = 0;
#pragma unroll
        for (int j = 0; j < 4; j++)
            u0 |= (__ldg(sp + (size_t)j * TT) > 0.5f ? 1u : 0u) << (8 * j);
#pragma unroll
        for (int j = 0; j < 4; j++)
            u1 |= (__ldg(sp + (size_t)(j + 4) * TT) > 0.5f ? 1u : 0u) << (8 * j);
        int g  = t & 7;
        int p  = (t >> 3) & 1;
        int mt = t >> 4;
        int pos = g * 8 + ((mt + 4 * (g & 1)) & 7);
        uint2 v; v.x = u0; v.y = u1;
        *(uint2*)(g_Aexp + ((size_t)cb * BB + b) * 1024 + pos * 16 + p * 8) = v;
        return;
    }

    // ---- prep (unchanged, validated) ----
    int rb = bid - PACK_BLOCKS;
    __shared__ uint8_t keptf[NCB];
    __shared__ uint8_t colss[KCAP];
    __shared__ int nks;

    keptf[tid] = (M[(size_t)(rb * 8) * CIN + tid * 8] != 0.0f) ? 1 : 0;
    __syncthreads();
    if (tid == 0) {
        int n = 0;
        for (int c = 0; c < NCB; c++)
            if (keptf[c] && n < KCAP) colss[n++] = (uint8_t)c;
        nks = n;
        g_nk[rb] = n;
        for (int k = n; k < KCAP; k++) colss[k] = 0;
    }
    __syncthreads();
    if (tid < KCAP) g_cols[rb * KCAP + tid] = colss[tid];

    int nk = nks;
    for (int idx = tid; idx < 8 * KCAP * 8; idx += 256) {
        int n = idx / (KCAP * 8), kk = idx % (KCAP * 8);
        int chunk = kk >> 5, w5 = kk & 31;
        int j = (w5 >> 2) & 3;
        int c = (w5 & 3) + 4 * (w5 >> 4);
        int blk = chunk * 4 + j;
        int8_t val = 0;
        if (blk < nk)
            val = (int8_t)__float2int_rn(W[(size_t)(rb * 8 + n) * CIN + colss[blk] * 8 + c]);
        g_Bc[(size_t)rb * (KCAP * 8 * 8) + n * (KCAP * 8) + kk] = val;
    }
}

// ---------------------------------------------------------------------------
// Kernel 2: block-sparse int8 MMA + fused integrate/fire/reset scan.
// CTA = (rb, b): M=128, N=8, K = nk*8 compacted.  4 warps, warp w owns
// m-tiles {2w, 2w+1}.  A pre-expanded in global; per-k-chunk double buffer.
// Mainloop per warp-iter: 2x LDS.128 + 2x LDS.32 + 2 MMA — no expand ALU.
// ---------------------------------------------------------------------------
__global__ void __launch_bounds__(NTHR) sgemm_scan_kernel(const int* __restrict__ scale_exp,
                                                          const int* __restrict__ texp,
                                                          float* __restrict__ out) {
    extern __shared__ __align__(16) uint8_t smem[];
    const uint32_t sb = smem_u32(smem);

    int tid = threadIdx.x, w = tid >> 5, lane = tid & 31;
    int g = lane >> 2, q = lane & 3;
    int rb = blockIdx.x;
    int b  = blockIdx.y;

    int nk = __ldg(&g_nk[rb]);
    int nkc = (nk + 3) >> 2;
    const uint8_t* colp = g_cols + rb * KCAP;

    // chunk gather: 4 blocks x 1024B expanded, 256 16B-units, 2 per thread
    auto load_chunk = [&](int ci) {
        uint32_t dst = sb + SAB_OFF + (uint32_t)(ci & 1) * CHUNK_BYTES;
#pragma unroll
        for (int i = 0; i < 2; i++) {
            int e = tid + i * NTHR;
            int blk = e >> 6, o = e & 63;
            int col = __ldg(colp + ci * 4 + blk);
            cp_async16(dst + blk * BLK_PITCH + o * 16,
                       g_Aexp + ((size_t)col * BB + b) * 1024 + o * 16);
        }
    };

    // Prologue: B (192 16B-units) + chunk 0, one group
    {
        const char* Bg = (const char*)g_Bc + (size_t)rb * (KCAP * 8 * 8);
#pragma unroll
        for (int i = 0; i < 2; i++) {
            int e = tid + i * NTHR;
            if (e < 8 * (KCAP * 8) / 16) {
                int n = e / (KCAP * 8 / 16), o = e % (KCAP * 8 / 16);
                cp_async16(sb + SB_OFF + n * B_PITCH + o * 16, Bg + n * (KCAP * 8) + o * 16);
            }
        }
        load_chunk(0);
    }
    cp_commit();

    int acc[2][4] = {{0, 0, 0, 0}, {0, 0, 0, 0}};
    const uint8_t* sBrow = smem + SB_OFF + g * B_PITCH;
    // thread's A unit offsets within a chunk buffer (block q), for mt = 2w, 2w+1
    const int mt0 = 2 * w;
    const uint32_t aoff0 = q * BLK_PITCH + (g * 8 + ((mt0 + 4 * (g & 1)) & 7)) * 16;
    const uint32_t aoff1 = q * BLK_PITCH + (g * 8 + (((mt0 + 1) + 4 * (g & 1)) & 7)) * 16;

    for (int it = 0; it < nkc; it++) {
        cp_wait0();
        __syncthreads();            // chunk `it` staged & visible; prev compute done
        if (it + 1 < nkc) load_chunk(it + 1);
        cp_commit();                // (empty group in tail keeps wait count aligned)

        uint32_t b0 = *(const uint32_t*)(sBrow + it * 32 + q * 4);
        uint32_t b1 = *(const uint32_t*)(sBrow + it * 32 + q * 4 + 16);
        const uint8_t* buf = smem + SAB_OFF + (it & 1) * CHUNK_BYTES;
        uint4 v0 = *(const uint4*)(buf + aoff0);
        uint4 v1 = *(const uint4*)(buf + aoff1);
        mma_s8(acc[0], v0.x, v0.z, v0.y, v0.w, b0, b1);
        mma_s8(acc[1], v1.x, v1.z, v1.y, v1.w, b0, b1);
    }
    __syncthreads();   // A buffers dead; reuse as C staging

    // Stage C into smem fp32 (exact, |acc| < 2^18)
    float* sC = (float*)(smem + SAB_OFF);
#pragma unroll
    for (int mtl = 0; mtl < 2; mtl++) {
        int row = (mt0 + mtl) * 16 + g;
        float* dst = sC + row * C_PITCH;
        dst[2 * q]                   = (float)acc[mtl][0];
        dst[2 * q + 1]               = (float)acc[mtl][1];
        dst[8 * C_PITCH + 2 * q]     = (float)acc[mtl][2];
        dst[8 * C_PITCH + 2 * q + 1] = (float)acc[mtl][3];
    }
    __syncthreads();

    // Integrate / fire / reset: 8 scans (8 channels)
    uint32_t* sBits = (uint32_t*)(smem + SBITS_OFF);
    if (tid < 8) {
        float scale = exp2f((float)scale_exp[rb * 8 + tid]);
        float thr   = exp2f((float)texp[0]);
        float a = 0.0f;
        uint32_t bits[4] = {0, 0, 0, 0};
        const float* c = sC + tid;
#pragma unroll 4
        for (int t = 0; t < TT; t++) {
            a = fmaf(c[t * C_PITCH], scale, a);
            if (a >= thr) { bits[t >> 5] |= 1u << (t & 31); a = 0.0f; }
        }
        sBits[tid * 4 + 0] = bits[0];
        sBits[tid * 4 + 1] = bits[1];
        sBits[tid * 4 + 2] = bits[2];
        sBits[tid * 4 + 3] = bits[3];
    }
    __syncthreads();

    // Output: out[b][rb*8+ch][t], 256 float4 stores (2 per thread)
#pragma unroll
    for (int i = 0; i < 2; i++) {
        int e = tid + i * NTHR;
        int ch = e >> 5, t4 = e & 31;
        uint32_t word = sBits[ch * 4 + (t4 >> 3)];
        float4 vv;
        vv.x = (word >> ((t4 * 4 + 0) & 31)) & 1 ? 1.0f : 0.0f;
        vv.y = (word >> ((t4 * 4 + 1) & 31)) & 1 ? 1.0f : 0.0f;
        vv.z = (word >> ((t4 * 4 + 2) & 31)) & 1 ? 1.0f : 0.0f;
        vv.w = (word >> ((t4 * 4 + 3) & 31)) & 1 ? 1.0f : 0.0f;
        *(float4*)(out + ((size_t)b * COUT + rb * 8 + ch) * TT + t4 * 4) = vv;
    }
}

// ---------------------------------------------------------------------------
// Inputs: spikes f32 [64,2048,128], weights f32 [2048,2048], mask f32
// [2048,2048], scale_exp i32 [2048], threshold_exp i32 [1].
// Output: f32 [64,2048,128].
// ---------------------------------------------------------------------------
extern "C" void kernel_launch(void* const* d_in, const int* in_sizes, int n_in,
                              void* d_out, int out_size) {
    const float* spikes    = (const float*)d_in[0];
    const float* weights   = (const float*)d_in[1];
    const float* mask      = (const float*)d_in[2];
    const int*   scale_exp = (const int*)d_in[3];
    const int*   texp      = (const int*)d_in[4];
    float*       out       = (float*)d_out;

    pack_prep_kernel<<<PACK_BLOCKS + NRB, 256>>>(spikes, weights, mask);
    sgemm_scan_kernel<<<dim3(NRB, BB), NTHR, SMEM_G>>>(scale_exp, texp, out);
}

// round 13
// speedup vs baseline: 1.0175x; 1.0175x over previous
#include <cuda_runtime.h>
#include <stdint.h>

// Problem shape (fixed)
#define BB    64
#define TT    128
#define CIN   2048
#define COUT  2048
#define NRB   256          // COUT/8 block-rows
#define NCB   256          // CIN/8  block-cols
#define KCAP  48           // max kept blocks per block-row (validated R11)
#define MB    2            // batches per GEMM CTA
#define NTHR  128          // threads per GEMM CTA (4 warps)

#define PACK_BLOCKS 8192   // fused kernel: first 8192 CTAs pack, next 256 prep

#define B_PITCH 400                    // bytes per n-row in smem B (384 data + 16 pad)
#define A_PITCH (MB * 128 + 16)        // 272 bytes per block-col in smem A (8B-aligned)
#define C_PITCH 9                      // fp32 words per staged C row
#define CBATCH  (TT * C_PITCH + 8)     // 1160 words per batch in C staging
#define COLSTRIDE ((size_t)BB * 128)   // bytes per block-column in g_packed2

// Dynamic smem layout (A region reused for C staging after the mainloop)
#define SA_OFF    0
#define SA_BYTES  (KCAP * A_PITCH)            // 13056 (>= MB*CBATCH*4 = 9280)
#define SB_OFF    SA_BYTES
#define SBITS_OFF (SB_OFF + 8 * B_PITCH)      // 16256
#define SMEM_G    (SBITS_OFF + 256)           // 16512 -> 14 CTAs/SM (228KB cap)

// Scratch (static device globals — no runtime allocation)
// g_packed2[cb][b][off]: off = h*64 + g*8 + mt*2 + p  for t = h*64 + mt*16 + p*8 + g
// -> thread (g) finds its 4 fragment u16s (mt=0..3, rows r/r+8) in ONE aligned 8B word.
__device__ __align__(16) uint8_t g_packed2[(size_t)NCB * BB * TT]; // 2MB
__device__ __align__(16) int8_t  g_Bc[(size_t)NRB * 8 * KCAP * 8]; // interleaved k-order
__device__ uint8_t g_cols[NRB * KCAP];
__device__ int     g_nk[NRB];

// ---------------------------------------------------------------------------
// helpers
// ---------------------------------------------------------------------------
__device__ __forceinline__ uint32_t smem_u32(const void* p) {
    uint32_t a;
    asm("{ .reg .u64 t; cvta.to.shared.u64 t, %1; cvt.u32.u64 %0, t; }" : "=r"(a) : "l"(p));
    return a;
}
__device__ __forceinline__ void cp_async16(uint32_t dst, const void* src) {
    asm volatile("cp.async.cg.shared.global [%0], [%1], 16;" :: "r"(dst), "l"(src) : "memory");
}
__device__ __forceinline__ void cp_commit_wait0() {
    asm volatile("cp.async.commit_group;" ::: "memory");
    asm volatile("cp.async.wait_group 0;" ::: "memory");
}
__device__ __forceinline__ void mma_s8(int* c, const uint32_t* a, const uint32_t* b) {
    asm volatile(
        "mma.sync.aligned.m16n8k32.row.col.s32.s8.s8.s32 "
        "{%0,%1,%2,%3}, {%4,%5,%6,%7}, {%8,%9}, {%0,%1,%2,%3};"
        : "+r"(c[0]), "+r"(c[1]), "+r"(c[2]), "+r"(c[3])
        : "r"(a[0]), "r"(a[1]), "r"(a[2]), "r"(a[3]), "r"(b[0]), "r"(b[1]));
}
// expand 4 bits at offset sh of v to 4 bytes of 0/1
__device__ __forceinline__ uint32_t expand_nib(uint32_t v, uint32_t sh) {
    return (((v >> sh) & 0xFu) * 0x00204081u) & 0x01010101u;
}
// exact 2^e for |e| <= 126
__device__ __forceinline__ float exp2i(int e) {
    return __int_as_float((e + 127) << 23);
}

// ---------------------------------------------------------------------------
// Kernel 1 (fused): CTAs [0, PACK_BLOCKS) pack spikes into g_packed2;
// CTAs [PACK_BLOCKS, PACK_BLOCKS+NRB) do the per-block-row weight compaction.
// ---------------------------------------------------------------------------
__global__ void __launch_bounds__(256) pack_prep_kernel(const float* __restrict__ spikes,
                                                        const float* __restrict__ W,
                                                        const float* __restrict__ M) {
    int bid = blockIdx.x;
    int tid = threadIdx.x;

    if (bid < PACK_BLOCKS) {
        // ---- pack: one byte per (cb, b, t); fragment-grouped layout ----
        int b  = bid >> 7;                 // 64 batches
        int cb = (bid & 127) * 2 + (tid >> 7);
        int t  = tid & 127;
        const float* sp = spikes + ((size_t)b * CIN + cb * 8) * TT + t;
        uint32_t byte = 0;
#pragma unroll
        for (int j = 0; j < 8; j++)
            byte |= (__ldg(sp + (size_t)j * TT) > 0.5f ? 1u : 0u) << j;
        // t = h*64 + mt*16 + p*8 + g  ->  off = h*64 + g*8 + mt*2 + p
        int h  = t >> 6;
        int mt = (t >> 4) & 3;
        int p  = (t >> 3) & 1;
        int g  = t & 7;
        int off = h * 64 + g * 8 + mt * 2 + p;
        g_packed2[(size_t)cb * COLSTRIDE + b * 128 + off] = (uint8_t)byte;
        return;
    }

    // ---- prep (unchanged, validated) ----
    int rb = bid - PACK_BLOCKS;
    __shared__ uint8_t keptf[NCB];
    __shared__ uint8_t colss[KCAP];
    __shared__ int nks;

    keptf[tid] = (M[(size_t)(rb * 8) * CIN + tid * 8] != 0.0f) ? 1 : 0;
    __syncthreads();
    if (tid == 0) {
        int n = 0;
        for (int c = 0; c < NCB; c++)
            if (keptf[c] && n < KCAP) colss[n++] = (uint8_t)c;
        nks = n;
        g_nk[rb] = n;
        for (int k = n; k < KCAP; k++) colss[k] = 0;
    }
    __syncthreads();
    if (tid < KCAP) g_cols[rb * KCAP + tid] = colss[tid];

    int nk = nks;
    for (int idx = tid; idx < 8 * KCAP * 8; idx += 256) {
        int n = idx / (KCAP * 8), kk = idx % (KCAP * 8);
        int chunk = kk >> 5, w5 = kk & 31;
        int j = (w5 >> 2) & 3;
        int c = (w5 & 3) + 4 * (w5 >> 4);
        int blk = chunk * 4 + j;
        int8_t val = 0;
        if (blk < nk)
            val = (int8_t)__float2int_rn(W[(size_t)(rb * 8 + n) * CIN + colss[blk] * 8 + c]);
        g_Bc[(size_t)rb * (KCAP * 8 * 8) + n * (KCAP * 8) + kk] = val;
    }
}

// ---------------------------------------------------------------------------
// Kernel 2: block-sparse int8 MMA + fused integrate/fire/reset scan.
// CTA = (rb, 2-batch group): M=256, N=8, K = nk*8 compacted.  4 warps:
// warp w = batch w>>1, row-half w&1; thread q owns block-col it*4+q.
// All 4 A fragments of an iteration come from ONE LDS.64.
// Scans distributed over all 4 warps (4 lanes each) to balance SMSPs.
// ---------------------------------------------------------------------------
__global__ void __launch_bounds__(NTHR) sgemm_scan_kernel(const int* __restrict__ scale_exp,
                                                          const int* __restrict__ texp,
                                                          float* __restrict__ out) {
    extern __shared__ __align__(16) uint8_t smem[];
    const uint32_t sbA = smem_u32(smem);

    int tid = threadIdx.x, w = tid >> 5, lane = tid & 31;
    int g = lane >> 2, q = lane & 3;
    int rb = blockIdx.x;
    int b0 = blockIdx.y * MB;

    int nk = __ldg(&g_nk[rb]);
    int nkc = (nk + 3) >> 2;
    const uint8_t* colp = g_cols + rb * KCAP;

    // Stage B (8 rows x KCAP*8 bytes) + A (nk*256B, coalesced 256B per kept col)
    {
        const char* Bg = (const char*)g_Bc + (size_t)rb * (KCAP * 8 * 8);
#pragma unroll
        for (int i = 0; i < 2; i++) {
            int e = tid + i * NTHR;                 // 192 chunks of 16B
            if (e < 8 * (KCAP * 8) / 16) {
                int n = e / (KCAP * 8 / 16), o = e % (KCAP * 8 / 16);
                cp_async16(sbA + SB_OFF + n * B_PITCH + o * 16, Bg + n * (KCAP * 8) + o * 16);
            }
        }
        int nk16 = nk * 16;
        const char* Ag = (const char*)g_packed2 + (size_t)b0 * 128;
        for (int e = tid; e < nk16; e += NTHR) {
            int blk = e >> 4, o2 = e & 15;
            int col = __ldg(colp + blk);
            cp_async16(sbA + SA_OFF + blk * A_PITCH + o2 * 16,
                       Ag + (size_t)col * COLSTRIDE + o2 * 16);
        }
    }
    cp_commit_wait0();
    __syncthreads();

    int acc[4][4];
#pragma unroll
    for (int i = 0; i < 4; i++)
#pragma unroll
        for (int j = 0; j < 4; j++) acc[i][j] = 0;

    // warp w: batch w>>1 (offset *128 in block-col), half h = w&1 (offset *64)
    const uint8_t* sA = smem + SA_OFF + (w >> 1) * 128 + (w & 1) * 64 + g * 8;
    const uint8_t* sBrow = smem + SB_OFF + g * B_PITCH;

    for (int it = 0; it < nkc; it++) {
        uint32_t bf[2];
        bf[0] = *(const uint32_t*)(sBrow + it * 32 + q * 4);
        bf[1] = *(const uint32_t*)(sBrow + it * 32 + q * 4 + 16);
        uint2 v2 = *(const uint2*)(sA + (it * 4 + q) * A_PITCH);  // 4 u16 fragments
#pragma unroll
        for (int mt = 0; mt < 4; mt++) {
            uint32_t src = (mt & 1) ? ((mt & 2) ? (v2.y >> 16) : (v2.x >> 16))
                                    : ((mt & 2) ? v2.y : v2.x);
            uint32_t af[4];
            af[0] = expand_nib(src, 0);   // row r,   ch 0..3
            af[1] = expand_nib(src, 8);   // row r+8, ch 0..3
            af[2] = expand_nib(src, 4);   // row r,   ch 4..7
            af[3] = expand_nib(src, 12);  // row r+8, ch 4..7
            mma_s8(acc[mt], af, bf);
        }
    }
    __syncthreads();   // A region dead; reuse as C staging

    // Stage C into smem fp32, per-batch padded (exact, |acc|<2^18)
    float* sC = (float*)(smem + SA_OFF);
#pragma unroll
    for (int mt = 0; mt < 4; mt++) {
        int lr = (w & 1) * 64 + mt * 16 + g;        // local row within batch w>>1
        float* dst = sC + (size_t)(w >> 1) * CBATCH + lr * C_PITCH;
        dst[2 * q]                   = (float)acc[mt][0];
        dst[2 * q + 1]               = (float)acc[mt][1];
        dst[8 * C_PITCH + 2 * q]     = (float)acc[mt][2];
        dst[8 * C_PITCH + 2 * q + 1] = (float)acc[mt][3];
    }
    __syncthreads();

    // Integrate / fire / reset: 16 scans (2 batches x 8 channels),
    // spread as 4 scans per warp so every SMSP carries equal scan load.
    uint32_t* sBits = (uint32_t*)(smem + SBITS_OFF);
    if (lane < 4) {
        int s  = w * 4 + lane;          // 0..15
        int ch = s & 7, bi = s >> 3;
        float scale = exp2i(__ldg(&scale_exp[rb * 8 + ch]));
        float thr   = exp2i(__ldg(&texp[0]));
        float a = 0.0f;
        uint32_t bits[4] = {0, 0, 0, 0};
        const float* c = sC + (size_t)bi * CBATCH + ch;
#pragma unroll 4
        for (int t = 0; t < TT; t++) {
            a = fmaf(c[t * C_PITCH], scale, a);
            if (a >= thr) { bits[t >> 5] |= 1u << (t & 31); a = 0.0f; }
        }
        sBits[s * 4 + 0] = bits[0];
        sBits[s * 4 + 1] = bits[1];
        sBits[s * 4 + 2] = bits[2];
        sBits[s * 4 + 3] = bits[3];
    }
    __syncthreads();

    // Output: out[b0+bi][rb*8+ch][t], float4 stores (512 total, 4 per thread)
#pragma unroll
    for (int i = 0; i < 4; i++) {
        int e = tid + i * NTHR;
        int r = e >> 5, t4 = e & 31;       // r = bi*8+ch
        int bi = r >> 3, ch = r & 7;
        uint32_t word = sBits[r * 4 + (t4 >> 3)];
        float4 vv;
        vv.x = (word >> ((t4 * 4 + 0) & 31)) & 1 ? 1.0f : 0.0f;
        vv.y = (word >> ((t4 * 4 + 1) & 31)) & 1 ? 1.0f : 0.0f;
        vv.z = (word >> ((t4 * 4 + 2) & 31)) & 1 ? 1.0f : 0.0f;
        vv.w = (word >> ((t4 * 4 + 3) & 31)) & 1 ? 1.0f : 0.0f;
        *(float4*)(out + ((size_t)(b0 + bi) * COUT + rb * 8 + ch) * TT + t4 * 4) = vv;
    }
}

// ---------------------------------------------------------------------------
// Inputs: spikes f32 [64,2048,128], weights f32 [2048,2048], mask f32
// [2048,2048], scale_exp i32 [2048], threshold_exp i32 [1].
// Output: f32 [64,2048,128].
// ---------------------------------------------------------------------------
extern "C" void kernel_launch(void* const* d_in, const int* in_sizes, int n_in,
                              void* d_out, int out_size) {
    const float* spikes    = (const float*)d_in[0];
    const float* weights   = (const float*)d_in[1];
    const float* mask      = (const float*)d_in[2];
    const int*   scale_exp = (const int*)d_in[3];
    const int*   texp      = (const int*)d_in[4];
    float*       out       = (float*)d_out;

    pack_prep_kernel<<<PACK_BLOCKS + NRB, 256>>>(spikes, weights, mask);
    sgemm_scan_kernel<<<dim3(NRB, BB / MB), NTHR, SMEM_G>>>(scale_exp, texp, out);
}

// round 14
// speedup vs baseline: 1.1958x; 1.1752x over previous
#include <cuda_runtime.h>
#include <stdint.h>

// Problem shape (fixed)
#define BB    64
#define TT    128
#define CIN   2048
#define COUT  2048
#define NRB   256          // COUT/8 block-rows
#define NCB   256          // CIN/8  block-cols
#define KCAP  48           // max kept blocks per block-row (validated R11)
#define MB    2            // batches per GEMM CTA
#define NTHR  128          // threads per GEMM CTA (4 warps)

#define PACK_BLOCKS 8192   // fused kernel: first 8192 CTAs pack, next 256 prep

#define B_PITCH 528                    // bytes per n-row in smem B (known-good R11)
#define A_PITCH (MB * 128 + 16)        // 272 bytes per block-col in smem A
#define C_PITCH 9                      // fp32 words per staged C row
#define CBATCH  (TT * C_PITCH + 8)     // 1160 words per batch in C staging
#define COLSTRIDE ((size_t)BB * 128)   // bytes per block-column in g_packed2

// Dynamic smem layout (A region reused for C staging after the mainloop)
#define SA_OFF    0
#define SA_BYTES  (KCAP * A_PITCH)            // 13056 (>= MB*CBATCH*4 = 9280)
#define SB_OFF    SA_BYTES
#define SBITS_OFF (SB_OFF + 8 * B_PITCH)      // 17280
#define SMEM_G    (SBITS_OFF + 256)           // 17536 -> 13 CTAs/SM

// Scratch (static device globals — no runtime allocation)
// g_packed2[cb][b][off]: off = h*64 + g*8 + mt*2 + p  for t = h*64 + mt*16 + p*8 + g
// -> thread (g) finds its 4 fragment u16s (mt=0..3, rows r/r+8) in ONE aligned 8B word.
__device__ __align__(16) uint8_t g_packed2[(size_t)NCB * BB * TT]; // 2MB
__device__ __align__(16) int8_t  g_Bc[(size_t)NRB * 8 * KCAP * 8]; // interleaved k-order
__device__ uint8_t g_cols[NRB * KCAP];
__device__ int     g_nk[NRB];

// ---------------------------------------------------------------------------
// helpers
// ---------------------------------------------------------------------------
__device__ __forceinline__ uint32_t smem_u32(const void* p) {
    uint32_t a;
    asm("{ .reg .u64 t; cvta.to.shared.u64 t, %1; cvt.u32.u64 %0, t; }" : "=r"(a) : "l"(p));
    return a;
}
__device__ __forceinline__ void cp_async16(uint32_t dst, const void* src) {
    asm volatile("cp.async.cg.shared.global [%0], [%1], 16;" :: "r"(dst), "l"(src) : "memory");
}
__device__ __forceinline__ void cp_commit_wait0() {
    asm volatile("cp.async.commit_group;" ::: "memory");
    asm volatile("cp.async.wait_group 0;" ::: "memory");
}
__device__ __forceinline__ void mma_s8(int* c, const uint32_t* a, const uint32_t* b) {
    asm volatile(
        "mma.sync.aligned.m16n8k32.row.col.s32.s8.s8.s32 "
        "{%0,%1,%2,%3}, {%4,%5,%6,%7}, {%8,%9}, {%0,%1,%2,%3};"
        : "+r"(c[0]), "+r"(c[1]), "+r"(c[2]), "+r"(c[3])
        : "r"(a[0]), "r"(a[1]), "r"(a[2]), "r"(a[3]), "r"(b[0]), "r"(b[1]));
}
// expand 4 bits at offset sh of v to 4 bytes of 0/1
__device__ __forceinline__ uint32_t expand_nib(uint32_t v, uint32_t sh) {
    return (((v >> sh) & 0xFu) * 0x00204081u) & 0x01010101u;
}
// exact 2^e for |e| <= 126
__device__ __forceinline__ float exp2i(int e) {
    return __int_as_float((e + 127) << 23);
}

// ---------------------------------------------------------------------------
// Kernel 1 (fused): CTAs [0, PACK_BLOCKS) pack spikes into g_packed2;
// CTAs [PACK_BLOCKS, PACK_BLOCKS+NRB) do the per-block-row weight compaction.
// ---------------------------------------------------------------------------
__global__ void __launch_bounds__(256) pack_prep_kernel(const float* __restrict__ spikes,
                                                        const float* __restrict__ W,
                                                        const float* __restrict__ M) {
    int bid = blockIdx.x;
    int tid = threadIdx.x;

    if (bid < PACK_BLOCKS) {
        // ---- pack: one byte per (cb, b, t); fragment-grouped layout ----
        int b  = bid >> 7;                 // 64 batches
        int cb = (bid & 127) * 2 + (tid >> 7);
        int t  = tid & 127;
        const float* sp = spikes + ((size_t)b * CIN + cb * 8) * TT + t;
        uint32_t byte = 0;
#pragma unroll
        for (int j = 0; j < 8; j++)
            byte |= (__ldg(sp + (size_t)j * TT) > 0.5f ? 1u : 0u) << j;
        // t = h*64 + mt*16 + p*8 + g  ->  off = h*64 + g*8 + mt*2 + p
        int h  = t >> 6;
        int mt = (t >> 4) & 3;
        int p  = (t >> 3) & 1;
        int g  = t & 7;
        int off = h * 64 + g * 8 + mt * 2 + p;
        g_packed2[(size_t)cb * COLSTRIDE + b * 128 + off] = (uint8_t)byte;
        return;
    }

    // ---- prep (unchanged, validated) ----
    int rb = bid - PACK_BLOCKS;
    __shared__ uint8_t keptf[NCB];
    __shared__ uint8_t colss[KCAP];
    __shared__ int nks;

    keptf[tid] = (M[(size_t)(rb * 8) * CIN + tid * 8] != 0.0f) ? 1 : 0;
    __syncthreads();
    if (tid == 0) {
        int n = 0;
        for (int c = 0; c < NCB; c++)
            if (keptf[c] && n < KCAP) colss[n++] = (uint8_t)c;
        nks = n;
        g_nk[rb] = n;
        for (int k = n; k < KCAP; k++) colss[k] = 0;
    }
    __syncthreads();
    if (tid < KCAP) g_cols[rb * KCAP + tid] = colss[tid];

    int nk = nks;
    for (int idx = tid; idx < 8 * KCAP * 8; idx += 256) {
        int n = idx / (KCAP * 8), kk = idx % (KCAP * 8);
        int chunk = kk >> 5, w5 = kk & 31;
        int j = (w5 >> 2) & 3;
        int c = (w5 & 3) + 4 * (w5 >> 4);
        int blk = chunk * 4 + j;
        int8_t val = 0;
        if (blk < nk)
            val = (int8_t)__float2int_rn(W[(size_t)(rb * 8 + n) * CIN + colss[blk] * 8 + c]);
        g_Bc[(size_t)rb * (KCAP * 8 * 8) + n * (KCAP * 8) + kk] = val;
    }
}

// ---------------------------------------------------------------------------
// Kernel 2: block-sparse int8 MMA + fused integrate/fire/reset scan.
// CTA = (rb, 2-batch group): M=256, N=8, K = nk*8 compacted.  4 warps:
// warp w = batch w>>1, row-half w&1; thread q owns block-col it*4+q.
// Software-pipelined: next iteration's LDS issued before this one's MMAs.
// ---------------------------------------------------------------------------
__global__ void __launch_bounds__(NTHR) sgemm_scan_kernel(const int* __restrict__ scale_exp,
                                                          const int* __restrict__ texp,
                                                          float* __restrict__ out) {
    extern __shared__ __align__(16) uint8_t smem[];
    const uint32_t sbA = smem_u32(smem);

    int tid = threadIdx.x, w = tid >> 5, lane = tid & 31;
    int g = lane >> 2, q = lane & 3;
    int rb = blockIdx.x;
    int b0 = blockIdx.y * MB;

    int nk = __ldg(&g_nk[rb]);
    int nkc = (nk + 3) >> 2;
    const uint8_t* colp = g_cols + rb * KCAP;

    // Stage B (8 rows x KCAP*8 bytes) + A (nk*256B, coalesced 256B per kept col)
    {
        const char* Bg = (const char*)g_Bc + (size_t)rb * (KCAP * 8 * 8);
#pragma unroll
        for (int i = 0; i < 2; i++) {
            int e = tid + i * NTHR;                 // 192 chunks of 16B
            if (e < 8 * (KCAP * 8) / 16) {
                int n = e / (KCAP * 8 / 16), o = e % (KCAP * 8 / 16);
                cp_async16(sbA + SB_OFF + n * B_PITCH + o * 16, Bg + n * (KCAP * 8) + o * 16);
            }
        }
        int nk16 = nk * 16;
        const char* Ag = (const char*)g_packed2 + (size_t)b0 * 128;
        for (int e = tid; e < nk16; e += NTHR) {
            int blk = e >> 4, o2 = e & 15;
            int col = __ldg(colp + blk);
            cp_async16(sbA + SA_OFF + blk * A_PITCH + o2 * 16,
                       Ag + (size_t)col * COLSTRIDE + o2 * 16);
        }
    }
    cp_commit_wait0();
    __syncthreads();

    int acc[4][4];
#pragma unroll
    for (int i = 0; i < 4; i++)
#pragma unroll
        for (int j = 0; j < 4; j++) acc[i][j] = 0;

    // warp w: batch w>>1 (offset *128 in block-col), half h = w&1 (offset *64)
    const uint8_t* sA = smem + SA_OFF + (w >> 1) * 128 + (w & 1) * 64 + g * 8;
    const uint8_t* sBrow = smem + SB_OFF + g * B_PITCH;

    // Software pipeline: preload it=0; in-loop, prefetch it+1 before MMAs.
    // One-past-end prefetch (it = nkc) stays inside the allocated smem
    // ((KCAP*4+3)*A_PITCH + 8 < SMEM_G) and its values are discarded.
    uint32_t bf0 = *(const uint32_t*)(sBrow + q * 4);
    uint32_t bf1 = *(const uint32_t*)(sBrow + q * 4 + 16);
    uint2 v2 = *(const uint2*)(sA + q * A_PITCH);

    for (int it = 0; it < nkc; it++) {
        uint32_t nbf0 = *(const uint32_t*)(sBrow + (it + 1) * 32 + q * 4);
        uint32_t nbf1 = *(const uint32_t*)(sBrow + (it + 1) * 32 + q * 4 + 16);
        uint2 nv2 = *(const uint2*)(sA + ((it + 1) * 4 + q) * A_PITCH);

        uint32_t bf[2] = {bf0, bf1};
#pragma unroll
        for (int mt = 0; mt < 4; mt++) {
            uint32_t src = (mt & 1) ? ((mt & 2) ? (v2.y >> 16) : (v2.x >> 16))
                                    : ((mt & 2) ? v2.y : v2.x);
            uint32_t af[4];
            af[0] = expand_nib(src, 0);   // row r,   ch 0..3
            af[1] = expand_nib(src, 8);   // row r+8, ch 0..3
            af[2] = expand_nib(src, 4);   // row r,   ch 4..7
            af[3] = expand_nib(src, 12);  // row r+8, ch 4..7
            mma_s8(acc[mt], af, bf);
        }
        bf0 = nbf0; bf1 = nbf1; v2 = nv2;
    }
    __syncthreads();   // A region dead; reuse as C staging

    // Stage C into smem fp32, per-batch padded (exact, |acc|<2^18)
    float* sC = (float*)(smem + SA_OFF);
#pragma unroll
    for (int mt = 0; mt < 4; mt++) {
        int lr = (w & 1) * 64 + mt * 16 + g;        // local row within batch w>>1
        float* dst = sC + (size_t)(w >> 1) * CBATCH + lr * C_PITCH;
        dst[2 * q]                   = (float)acc[mt][0];
        dst[2 * q + 1]               = (float)acc[mt][1];
        dst[8 * C_PITCH + 2 * q]     = (float)acc[mt][2];
        dst[8 * C_PITCH + 2 * q + 1] = (float)acc[mt][3];
    }
    __syncthreads();

    // Integrate / fire / reset: 16 scans (2 batches x 8 channels), ONE warp
    uint32_t* sBits = (uint32_t*)(smem + SBITS_OFF);
    if (tid < MB * 8) {
        int ch = tid & 7, bi = tid >> 3;
        float scale = exp2i(__ldg(&scale_exp[rb * 8 + ch]));
        float thr   = exp2i(__ldg(&texp[0]));
        float a = 0.0f;
        uint32_t bits[4] = {0, 0, 0, 0};
        const float* c = sC + (size_t)bi * CBATCH + ch;
#pragma unroll 4
        for (int t = 0; t < TT; t++) {
            a = fmaf(c[t * C_PITCH], scale, a);
            if (a >= thr) { bits[t >> 5] |= 1u << (t & 31); a = 0.0f; }
        }
        sBits[tid * 4 + 0] = bits[0];
        sBits[tid * 4 + 1] = bits[1];
        sBits[tid * 4 + 2] = bits[2];
        sBits[tid * 4 + 3] = bits[3];
    }
    __syncthreads();

    // Output: out[b0+bi][rb*8+ch][t], float4 stores (512 total, 4 per thread)
#pragma unroll
    for (int i = 0; i < 4; i++) {
        int e = tid + i * NTHR;
        int r = e >> 5, t4 = e & 31;       // r = bi*8+ch
        int bi = r >> 3, ch = r & 7;
        uint32_t word = sBits[r * 4 + (t4 >> 3)];
        float4 vv;
        vv.x = (word >> ((t4 * 4 + 0) & 31)) & 1 ? 1.0f : 0.0f;
        vv.y = (word >> ((t4 * 4 + 1) & 31)) & 1 ? 1.0f : 0.0f;
        vv.z = (word >> ((t4 * 4 + 2) & 31)) & 1 ? 1.0f : 0.0f;
        vv.w = (word >> ((t4 * 4 + 3) & 31)) & 1 ? 1.0f : 0.0f;
        *(float4*)(out + ((size_t)(b0 + bi) * COUT + rb * 8 + ch) * TT + t4 * 4) = vv;
    }
}

// ---------------------------------------------------------------------------
// Inputs: spikes f32 [64,2048,128], weights f32 [2048,2048], mask f32
// [2048,2048], scale_exp i32 [2048], threshold_exp i32 [1].
// Output: f32 [64,2048,128].
// ---------------------------------------------------------------------------
extern "C" void kernel_launch(void* const* d_in, const int* in_sizes, int n_in,
                              void* d_out, int out_size) {
    const float* spikes    = (const float*)d_in[0];
    const float* weights   = (const float*)d_in[1];
    const float* mask      = (const float*)d_in[2];
    const int*   scale_exp = (const int*)d_in[3];
    const int*   texp      = (const int*)d_in[4];
    float*       out       = (float*)d_out;

    pack_prep_kernel<<<PACK_BLOCKS + NRB, 256>>>(spikes, weights, mask);
    sgemm_scan_kernel<<<dim3(NRB, BB / MB), NTHR, SMEM_G>>>(scale_exp, texp, out);
}

// round 15
// speedup vs baseline: 1.2098x; 1.0117x over previous
#include <cuda_runtime.h>
#include <stdint.h>

// Problem shape (fixed)
#define BB    64
#define TT    128
#define CIN   2048
#define COUT  2048
#define NRB   256          // COUT/8 block-rows
#define NCB   256          // CIN/8  block-cols
#define KCAP  48           // max kept blocks per block-row (validated R11)
#define MB    2            // batches per GEMM CTA
#define NTHR  128          // threads per GEMM CTA (4 warps)

#define PACK_BLOCKS 8192   // fused kernel: first 8192 CTAs pack, next 256 prep

#define B_PITCH 400                    // bytes per n-row in smem B (384 data + 16 pad)
#define A_PITCH (MB * 128 + 16)        // 272 bytes per block-col in smem A
#define C_PITCH 10                     // fp32 words per staged C row (even -> STS.64)
#define CBATCH  (TT * C_PITCH + 8)     // 1288 words per batch in C staging
#define COLSTRIDE ((size_t)BB * 128)   // bytes per block-column in g_packed2

// Dynamic smem layout (A region reused for C staging after the mainloop)
#define SA_OFF    0
#define SA_BYTES  (KCAP * A_PITCH)            // 13056 (>= MB*CBATCH*4 = 10304)
#define SB_OFF    SA_BYTES
#define SBITS_OFF (SB_OFF + 8 * B_PITCH)      // 16256
#define SMEM_G    (SBITS_OFF + 256)           // 16512 -> 14 CTAs/SM

// Scratch (static device globals — no runtime allocation)
// g_packed2[cb][b][off]: off = h*64 + g*8 + mt*2 + p  for t = h*64 + mt*16 + p*8 + g
__device__ __align__(16) uint8_t g_packed2[(size_t)NCB * BB * TT]; // 2MB
__device__ __align__(16) int8_t  g_Bc[(size_t)NRB * 8 * KCAP * 8]; // interleaved k-order
__device__ uint8_t g_cols[NRB * KCAP];
__device__ int     g_nk[NRB];

// nibble -> float4 of 0/1 (bit j -> component j); static image data, L1-resident
__device__ const float4 g_lut[16] = {
    {0,0,0,0},{1,0,0,0},{0,1,0,0},{1,1,0,0},
    {0,0,1,0},{1,0,1,0},{0,1,1,0},{1,1,1,0},
    {0,0,0,1},{1,0,0,1},{0,1,0,1},{1,1,0,1},
    {0,0,1,1},{1,0,1,1},{0,1,1,1},{1,1,1,1}
};

// ---------------------------------------------------------------------------
// helpers
// ---------------------------------------------------------------------------
__device__ __forceinline__ uint32_t smem_u32(const void* p) {
    uint32_t a;
    asm("{ .reg .u64 t; cvta.to.shared.u64 t, %1; cvt.u32.u64 %0, t; }" : "=r"(a) : "l"(p));
    return a;
}
__device__ __forceinline__ void cp_async16(uint32_t dst, const void* src) {
    asm volatile("cp.async.cg.shared.global [%0], [%1], 16;" :: "r"(dst), "l"(src) : "memory");
}
__device__ __forceinline__ void cp_commit_wait0() {
    asm volatile("cp.async.commit_group;" ::: "memory");
    asm volatile("cp.async.wait_group 0;" ::: "memory");
}
__device__ __forceinline__ void mma_s8(int* c, const uint32_t* a, const uint32_t* b) {
    asm volatile(
        "mma.sync.aligned.m16n8k32.row.col.s32.s8.s8.s32 "
        "{%0,%1,%2,%3}, {%4,%5,%6,%7}, {%8,%9}, {%0,%1,%2,%3};"
        : "+r"(c[0]), "+r"(c[1]), "+r"(c[2]), "+r"(c[3])
        : "r"(a[0]), "r"(a[1]), "r"(a[2]), "r"(a[3]), "r"(b[0]), "r"(b[1]));
}
// expand 4 bits at offset sh of v to 4 bytes of 0/1
__device__ __forceinline__ uint32_t expand_nib(uint32_t v, uint32_t sh) {
    return (((v >> sh) & 0xFu) * 0x00204081u) & 0x01010101u;
}
// exact 2^e for |e| <= 126
__device__ __forceinline__ float exp2i(int e) {
    return __int_as_float((e + 127) << 23);
}

// ---------------------------------------------------------------------------
// Kernel 1 (fused): CTAs [0, PACK_BLOCKS) pack spikes into g_packed2;
// CTAs [PACK_BLOCKS, PACK_BLOCKS+NRB) do the per-block-row weight compaction.
// ---------------------------------------------------------------------------
__global__ void __launch_bounds__(256) pack_prep_kernel(const float* __restrict__ spikes,
                                                        const float* __restrict__ W,
                                                        const float* __restrict__ M) {
    int bid = blockIdx.x;
    int tid = threadIdx.x;

    if (bid < PACK_BLOCKS) {
        // ---- pack: one byte per (cb, b, t); fragment-grouped layout ----
        int b  = bid >> 7;                 // 64 batches
        int cb = (bid & 127) * 2 + (tid >> 7);
        int t  = tid & 127;
        const float* sp = spikes + ((size_t)b * CIN + cb * 8) * TT + t;
        uint32_t byte = 0;
#pragma unroll
        for (int j = 0; j < 8; j++)
            byte |= (__ldg(sp + (size_t)j * TT) > 0.5f ? 1u : 0u) << j;
        // t = h*64 + mt*16 + p*8 + g  ->  off = h*64 + g*8 + mt*2 + p
        int h  = t >> 6;
        int mt = (t >> 4) & 3;
        int p  = (t >> 3) & 1;
        int g  = t & 7;
        int off = h * 64 + g * 8 + mt * 2 + p;
        g_packed2[(size_t)cb * COLSTRIDE + b * 128 + off] = (uint8_t)byte;
        return;
    }

    // ---- prep (unchanged, validated) ----
    int rb = bid - PACK_BLOCKS;
    __shared__ uint8_t keptf[NCB];
    __shared__ uint8_t colss[KCAP];
    __shared__ int nks;

    keptf[tid] = (M[(size_t)(rb * 8) * CIN + tid * 8] != 0.0f) ? 1 : 0;
    __syncthreads();
    if (tid == 0) {
        int n = 0;
        for (int c = 0; c < NCB; c++)
            if (keptf[c] && n < KCAP) colss[n++] = (uint8_t)c;
        nks = n;
        g_nk[rb] = n;
        for (int k = n; k < KCAP; k++) colss[k] = 0;
    }
    __syncthreads();
    if (tid < KCAP) g_cols[rb * KCAP + tid] = colss[tid];

    int nk = nks;
    for (int idx = tid; idx < 8 * KCAP * 8; idx += 256) {
        int n = idx / (KCAP * 8), kk = idx % (KCAP * 8);
        int chunk = kk >> 5, w5 = kk & 31;
        int j = (w5 >> 2) & 3;
        int c = (w5 & 3) + 4 * (w5 >> 4);
        int blk = chunk * 4 + j;
        int8_t val = 0;
        if (blk < nk)
            val = (int8_t)__float2int_rn(W[(size_t)(rb * 8 + n) * CIN + colss[blk] * 8 + c]);
        g_Bc[(size_t)rb * (KCAP * 8 * 8) + n * (KCAP * 8) + kk] = val;
    }
}

// ---------------------------------------------------------------------------
// Kernel 2: block-sparse int8 MMA + fused integrate/fire/reset scan.
// CTA = (rb, 2-batch group): M=256, N=8, K = nk*8 compacted.  4 warps:
// warp w = batch w>>1, row-half w&1; thread q owns block-col it*4+q.
// Mainloop identical to R11 (validated twice at 69.6us); epilogue slimmed.
// ---------------------------------------------------------------------------
__global__ void __launch_bounds__(NTHR) sgemm_scan_kernel(const int* __restrict__ scale_exp,
                                                          const int* __restrict__ texp,
                                                          float* __restrict__ out) {
    extern __shared__ __align__(16) uint8_t smem[];
    const uint32_t sbA = smem_u32(smem);

    int tid = threadIdx.x, w = tid >> 5, lane = tid & 31;
    int g = lane >> 2, q = lane & 3;
    int rb = blockIdx.x;
    int b0 = blockIdx.y * MB;

    int nk = __ldg(&g_nk[rb]);
    int nkc = (nk + 3) >> 2;
    const uint8_t* colp = g_cols + rb * KCAP;

    // Stage B (8 rows x KCAP*8 bytes) + A (nk*256B, coalesced 256B per kept col)
    {
        const char* Bg = (const char*)g_Bc + (size_t)rb * (KCAP * 8 * 8);
#pragma unroll
        for (int i = 0; i < 2; i++) {
            int e = tid + i * NTHR;                 // 192 chunks of 16B
            if (e < 8 * (KCAP * 8) / 16) {
                int n = e / (KCAP * 8 / 16), o = e % (KCAP * 8 / 16);
                cp_async16(sbA + SB_OFF + n * B_PITCH + o * 16, Bg + n * (KCAP * 8) + o * 16);
            }
        }
        int nk16 = nk * 16;
        const char* Ag = (const char*)g_packed2 + (size_t)b0 * 128;
        for (int e = tid; e < nk16; e += NTHR) {
            int blk = e >> 4, o2 = e & 15;
            int col = __ldg(colp + blk);
            cp_async16(sbA + SA_OFF + blk * A_PITCH + o2 * 16,
                       Ag + (size_t)col * COLSTRIDE + o2 * 16);
        }
    }
    cp_commit_wait0();
    __syncthreads();

    int acc[4][4];
#pragma unroll
    for (int i = 0; i < 4; i++)
#pragma unroll
        for (int j = 0; j < 4; j++) acc[i][j] = 0;

    // warp w: batch w>>1 (offset *128 in block-col), half h = w&1 (offset *64)
    const uint8_t* sA = smem + SA_OFF + (w >> 1) * 128 + (w & 1) * 64 + g * 8;
    const uint8_t* sBrow = smem + SB_OFF + g * B_PITCH;

    for (int it = 0; it < nkc; it++) {
        uint32_t bf[2];
        bf[0] = *(const uint32_t*)(sBrow + it * 32 + q * 4);
        bf[1] = *(const uint32_t*)(sBrow + it * 32 + q * 4 + 16);
        uint2 v2 = *(const uint2*)(sA + (it * 4 + q) * A_PITCH);  // 4 u16 fragments
#pragma unroll
        for (int mt = 0; mt < 4; mt++) {
            uint32_t src = (mt & 1) ? ((mt & 2) ? (v2.y >> 16) : (v2.x >> 16))
                                    : ((mt & 2) ? v2.y : v2.x);
            uint32_t af[4];
            af[0] = expand_nib(src, 0);   // row r,   ch 0..3
            af[1] = expand_nib(src, 8);   // row r+8, ch 0..3
            af[2] = expand_nib(src, 4);   // row r,   ch 4..7
            af[3] = expand_nib(src, 12);  // row r+8, ch 4..7
            mma_s8(acc[mt], af, bf);
        }
    }
    __syncthreads();   // A region dead; reuse as C staging

    // Stage C into smem fp32 via STS.64 pairs (exact, |acc|<2^18)
    float* sC = (float*)(smem + SA_OFF);
#pragma unroll
    for (int mt = 0; mt < 4; mt++) {
        int lr = (w & 1) * 64 + mt * 16 + g;        // local row within batch w>>1
        float* dst = sC + (size_t)(w >> 1) * CBATCH + lr * C_PITCH + 2 * q;
        float2 lo; lo.x = (float)acc[mt][0]; lo.y = (float)acc[mt][1];
        float2 hi; hi.x = (float)acc[mt][2]; hi.y = (float)acc[mt][3];
        *(float2*)dst = lo;
        *(float2*)(dst + 8 * C_PITCH) = hi;
    }
    __syncthreads();

    // Integrate / fire / reset: 16 scans (2 batches x 8 channels), ONE warp
    uint32_t* sBits = (uint32_t*)(smem + SBITS_OFF);
    if (tid < MB * 8) {
        int ch = tid & 7, bi = tid >> 3;
        float scale = exp2i(__ldg(&scale_exp[rb * 8 + ch]));
        float thr   = exp2i(__ldg(&texp[0]));
        float a = 0.0f;
        uint32_t bits[4] = {0, 0, 0, 0};
        const float* c = sC + (size_t)bi * CBATCH + ch;
#pragma unroll 4
        for (int t = 0; t < TT; t++) {
            a = fmaf(c[t * C_PITCH], scale, a);
            if (a >= thr) { bits[t >> 5] |= 1u << (t & 31); a = 0.0f; }
        }
        sBits[tid * 4 + 0] = bits[0];
        sBits[tid * 4 + 1] = bits[1];
        sBits[tid * 4 + 2] = bits[2];
        sBits[tid * 4 + 3] = bits[3];
    }
    __syncthreads();

    // Output: out[b0+bi][rb*8+ch][t]; nibble -> float4 via L1-resident LUT
#pragma unroll
    for (int i = 0; i < 4; i++) {
        int e = tid + i * NTHR;
        int r = e >> 5, t4 = e & 31;       // r = bi*8+ch
        int bi = r >> 3, ch = r & 7;
        uint32_t word = sBits[r * 4 + (t4 >> 3)];
        uint32_t nib = (word >> ((t4 & 7) * 4)) & 0xFu;
        float4 vv = __ldg(&g_lut[nib]);
        *(float4*)(out + ((size_t)(b0 + bi) * COUT + rb * 8 + ch) * TT + t4 * 4) = vv;
    }
}

// ---------------------------------------------------------------------------
// Inputs: spikes f32 [64,2048,128], weights f32 [2048,2048], mask f32
// [2048,2048], scale_exp i32 [2048], threshold_exp i32 [1].
// Output: f32 [64,2048,128].
// ---------------------------------------------------------------------------
extern "C" void kernel_launch(void* const* d_in, const int* in_sizes, int n_in,
                              void* d_out, int out_size) {
    const float* spikes    = (const float*)d_in[0];
    const float* weights   = (const float*)d_in[1];
    const float* mask      = (const float*)d_in[2];
    const int*   scale_exp = (const int*)d_in[3];
    const int*   texp      = (const int*)d_in[4];
    float*       out       = (float*)d_out;

    pack_prep_kernel<<<PACK_BLOCKS + NRB, 256>>>(spikes, weights, mask);
    sgemm_scan_kernel<<<dim3(NRB, BB / MB), NTHR, SMEM_G>>>(scale_exp, texp, out);
}

// round 16
// speedup vs baseline: 1.3512x; 1.1168x over previous
#include <cuda_runtime.h>
#include <stdint.h>

// Problem shape (fixed)
#define BB    64
#define TT    128
#define CIN   2048
#define COUT  2048
#define NRB   256          // COUT/8 block-rows
#define NCB   256          // CIN/8  block-cols
#define KCAP  48           // max kept blocks per block-row (validated R11)
#define MB    2            // batches per GEMM CTA
#define NTHR  128          // threads per GEMM CTA (4 warps)

#define B_PITCH 400                    // bytes per n-row in smem B (384 data + 16 pad)
#define A_PITCH (MB * 128 + 16)        // 272 bytes per block-col in smem A
#define C_PITCH 10                     // fp32 words per staged C row (even -> STS.64)
#define CBATCH  (TT * C_PITCH + 8)     // 1288 words per batch in C staging
#define COLSTRIDE ((size_t)BB * 128)   // bytes per block-column in g_packed2

// Dynamic smem layout.  A region reused for C staging after the mainloop;
// B region reused for the scan's bit buffer (B is dead after the mainloop).
#define SA_OFF    0
#define SA_BYTES  (KCAP * A_PITCH)            // 13056 (>= MB*CBATCH*4 = 10304)
#define SB_OFF    SA_BYTES
#define SBITS_OFF SB_OFF                      // overlay on dead B region (256B << 3200B)
#define SMEM_G    (SB_OFF + 8 * B_PITCH)      // 16256 -> 14 CTAs/SM (227.6KB)

// Scratch (static device globals — no runtime allocation)
// g_packed2[cb][b][off]: off = h*64 + g*8 + mt*2 + p  for t = h*64 + mt*16 + p*8 + g
__device__ __align__(16) uint8_t g_packed2[(size_t)NCB * BB * TT]; // 2MB
__device__ __align__(16) int8_t  g_Bc[(size_t)NRB * 8 * KCAP * 8]; // interleaved k-order
__device__ uint8_t g_cols[NRB * KCAP];
__device__ int     g_nk[NRB];

// nibble -> float4 of 0/1 (bit j -> component j); static image data, L1-resident
__device__ const float4 g_lut[16] = {
    {0,0,0,0},{1,0,0,0},{0,1,0,0},{1,1,0,0},
    {0,0,1,0},{1,0,1,0},{0,1,1,0},{1,1,1,0},
    {0,0,0,1},{1,0,0,1},{0,1,0,1},{1,1,0,1},
    {0,0,1,1},{1,0,1,1},{0,1,1,1},{1,1,1,1}
};

// ---------------------------------------------------------------------------
// helpers
// ---------------------------------------------------------------------------
__device__ __forceinline__ uint32_t smem_u32(const void* p) {
    uint32_t a;
    asm("{ .reg .u64 t; cvta.to.shared.u64 t, %1; cvt.u32.u64 %0, t; }" : "=r"(a) : "l"(p));
    return a;
}
__device__ __forceinline__ void cp_async16(uint32_t dst, const void* src) {
    asm volatile("cp.async.cg.shared.global [%0], [%1], 16;" :: "r"(dst), "l"(src) : "memory");
}
__device__ __forceinline__ void cp_commit_wait0() {
    asm volatile("cp.async.commit_group;" ::: "memory");
    asm volatile("cp.async.wait_group 0;" ::: "memory");
}
__device__ __forceinline__ void mma_s8(int* c, const uint32_t* a, const uint32_t* b) {
    asm volatile(
        "mma.sync.aligned.m16n8k32.row.col.s32.s8.s8.s32 "
        "{%0,%1,%2,%3}, {%4,%5,%6,%7}, {%8,%9}, {%0,%1,%2,%3};"
        : "+r"(c[0]), "+r"(c[1]), "+r"(c[2]), "+r"(c[3])
        : "r"(a[0]), "r"(a[1]), "r"(a[2]), "r"(a[3]), "r"(b[0]), "r"(b[1]));
}
// expand 4 bits at offset sh of v to 4 bytes of 0/1
__device__ __forceinline__ uint32_t expand_nib(uint32_t v, uint32_t sh) {
    return (((v >> sh) & 0xFu) * 0x00204081u) & 0x01010101u;
}
// exact 2^e for |e| <= 126
__device__ __forceinline__ float exp2i(int e) {
    return __int_as_float((e + 127) << 23);
}

// ---------------------------------------------------------------------------
// Kernel 1 (fused): CTAs [0, NRB) do per-block-row weight compaction (FIRST,
// so they run in wave 0 and hide under the pack waves); CTAs [NRB, NRB+8192)
// pack spikes into g_packed2.
// ---------------------------------------------------------------------------
__global__ void __launch_bounds__(256) pack_prep_kernel(const float* __restrict__ spikes,
                                                        const float* __restrict__ W,
                                                        const float* __restrict__ M) {
    int bid = blockIdx.x;
    int tid = threadIdx.x;

    if (bid >= NRB) {
        // ---- pack: one byte per (cb, b, t); fragment-grouped layout ----
        int pbid = bid - NRB;
        int b  = pbid >> 7;                 // 64 batches
        int cb = (pbid & 127) * 2 + (tid >> 7);
        int t  = tid & 127;
        const float* sp = spikes + ((size_t)b * CIN + cb * 8) * TT + t;
        uint32_t byte = 0;
#pragma unroll
        for (int j = 0; j < 8; j++)
            byte |= (__ldg(sp + (size_t)j * TT) > 0.5f ? 1u : 0u) << j;
        // t = h*64 + mt*16 + p*8 + g  ->  off = h*64 + g*8 + mt*2 + p
        int h  = t >> 6;
        int mt = (t >> 4) & 3;
        int p  = (t >> 3) & 1;
        int g  = t & 7;
        int off = h * 64 + g * 8 + mt * 2 + p;
        g_packed2[(size_t)cb * COLSTRIDE + b * 128 + off] = (uint8_t)byte;
        return;
    }

    // ---- prep: ballot-parallel compaction + weight gather ----
    int rb = bid;
    __shared__ uint8_t keptf[NCB];
    __shared__ uint8_t colss[KCAP];
    __shared__ int nks;

    keptf[tid] = (M[(size_t)(rb * 8) * CIN + tid * 8] != 0.0f) ? 1 : 0;
    __syncthreads();
    if (tid < 32) {
        int base = 0;
#pragma unroll
        for (int c8 = 0; c8 < 8; c8++) {
            int c = c8 * 32 + tid;
            bool k = keptf[c] != 0;
            unsigned m = __ballot_sync(0xFFFFFFFFu, k);
            int pos = base + __popc(m & ((1u << tid) - 1u));
            if (k && pos < KCAP) colss[pos] = (uint8_t)c;
            base += __popc(m);
        }
        int n = base < KCAP ? base : KCAP;
        if (tid == 0) { nks = n; g_nk[rb] = n; }
        // deterministic padding of unused slots
        for (int k = n + (int)tid; k < KCAP; k += 32) colss[k] = 0;
    }
    __syncthreads();
    if (tid < KCAP) g_cols[rb * KCAP + tid] = colss[tid];

    int nk = nks;
    for (int idx = tid; idx < 8 * KCAP * 8; idx += 256) {
        int n = idx / (KCAP * 8), kk = idx % (KCAP * 8);
        int chunk = kk >> 5, w5 = kk & 31;
        int j = (w5 >> 2) & 3;
        int c = (w5 & 3) + 4 * (w5 >> 4);
        int blk = chunk * 4 + j;
        int8_t val = 0;
        if (blk < nk)
            val = (int8_t)__float2int_rn(W[(size_t)(rb * 8 + n) * CIN + colss[blk] * 8 + c]);
        g_Bc[(size_t)rb * (KCAP * 8 * 8) + n * (KCAP * 8) + kk] = val;
    }
}

// ---------------------------------------------------------------------------
// Kernel 2: block-sparse int8 MMA + fused integrate/fire/reset scan.
// CTA = (rb, 2-batch group): M=256, N=8, K = nk*8 compacted.  4 warps:
// warp w = batch w>>1, row-half w&1; thread q owns block-col it*4+q.
// Mainloop identical to R11/R15 (validated at 68-70us).
// ---------------------------------------------------------------------------
__global__ void __launch_bounds__(NTHR) sgemm_scan_kernel(const int* __restrict__ scale_exp,
                                                          const int* __restrict__ texp,
                                                          float* __restrict__ out) {
    extern __shared__ __align__(16) uint8_t smem[];
    const uint32_t sbA = smem_u32(smem);

    int tid = threadIdx.x, w = tid >> 5, lane = tid & 31;
    int g = lane >> 2, q = lane & 3;
    int rb = blockIdx.x;
    int b0 = blockIdx.y * MB;

    int nk = __ldg(&g_nk[rb]);
    int nkc = (nk + 3) >> 2;
    const uint8_t* colp = g_cols + rb * KCAP;

    // Stage B (8 rows x KCAP*8 bytes) + A (nk*256B, coalesced 256B per kept col)
    {
        const char* Bg = (const char*)g_Bc + (size_t)rb * (KCAP * 8 * 8);
#pragma unroll
        for (int i = 0; i < 2; i++) {
            int e = tid + i * NTHR;                 // 192 chunks of 16B
            if (e < 8 * (KCAP * 8) / 16) {
                int n = e / (KCAP * 8 / 16), o = e % (KCAP * 8 / 16);
                cp_async16(sbA + SB_OFF + n * B_PITCH + o * 16, Bg + n * (KCAP * 8) + o * 16);
            }
        }
        int nk16 = nk * 16;
        const char* Ag = (const char*)g_packed2 + (size_t)b0 * 128;
        for (int e = tid; e < nk16; e += NTHR) {
            int blk = e >> 4, o2 = e & 15;
            int col = __ldg(colp + blk);
            cp_async16(sbA + SA_OFF + blk * A_PITCH + o2 * 16,
                       Ag + (size_t)col * COLSTRIDE + o2 * 16);
        }
    }
    cp_commit_wait0();
    __syncthreads();

    int acc[4][4];
#pragma unroll
    for (int i = 0; i < 4; i++)
#pragma unroll
        for (int j = 0; j < 4; j++) acc[i][j] = 0;

    // warp w: batch w>>1 (offset *128 in block-col), half h = w&1 (offset *64)
    const uint8_t* sA = smem + SA_OFF + (w >> 1) * 128 + (w & 1) * 64 + g * 8;
    const uint8_t* sBrow = smem + SB_OFF + g * B_PITCH;

    for (int it = 0; it < nkc; it++) {
        uint32_t bf[2];
        bf[0] = *(const uint32_t*)(sBrow + it * 32 + q * 4);
        bf[1] = *(const uint32_t*)(sBrow + it * 32 + q * 4 + 16);
        uint2 v2 = *(const uint2*)(sA + (it * 4 + q) * A_PITCH);  // 4 u16 fragments
#pragma unroll
        for (int mt = 0; mt < 4; mt++) {
            uint32_t src = (mt & 1) ? ((mt & 2) ? (v2.y >> 16) : (v2.x >> 16))
                                    : ((mt & 2) ? v2.y : v2.x);
            uint32_t af[4];
            af[0] = expand_nib(src, 0);   // row r,   ch 0..3
            af[1] = expand_nib(src, 8);   // row r+8, ch 0..3
            af[2] = expand_nib(src, 4);   // row r,   ch 4..7
            af[3] = expand_nib(src, 12);  // row r+8, ch 4..7
            mma_s8(acc[mt], af, bf);
        }
    }
    __syncthreads();   // A and B regions dead; reuse for C staging + bits

    // Stage C into smem fp32 via STS.64 pairs (exact, |acc|<2^18)
    float* sC = (float*)(smem + SA_OFF);
#pragma unroll
    for (int mt = 0; mt < 4; mt++) {
        int lr = (w & 1) * 64 + mt * 16 + g;        // local row within batch w>>1
        float* dst = sC + (size_t)(w >> 1) * CBATCH + lr * C_PITCH + 2 * q;
        float2 lo; lo.x = (float)acc[mt][0]; lo.y = (float)acc[mt][1];
        float2 hi; hi.x = (float)acc[mt][2]; hi.y = (float)acc[mt][3];
        *(float2*)dst = lo;
        *(float2*)(dst + 8 * C_PITCH) = hi;
    }
    __syncthreads();

    // Integrate / fire / reset: 16 scans (2 batches x 8 channels), ONE warp
    uint32_t* sBits = (uint32_t*)(smem + SBITS_OFF);
    if (tid < MB * 8) {
        int ch = tid & 7, bi = tid >> 3;
        float scale = exp2i(__ldg(&scale_exp[rb * 8 + ch]));
        float thr   = exp2i(__ldg(&texp[0]));
        float a = 0.0f;
        uint32_t bits[4] = {0, 0, 0, 0};
        const float* c = sC + (size_t)bi * CBATCH + ch;
#pragma unroll 4
        for (int t = 0; t < TT; t++) {
            a = fmaf(c[t * C_PITCH], scale, a);
            if (a >= thr) { bits[t >> 5] |= 1u << (t & 31); a = 0.0f; }
        }
        sBits[tid * 4 + 0] = bits[0];
        sBits[tid * 4 + 1] = bits[1];
        sBits[tid * 4 + 2] = bits[2];
        sBits[tid * 4 + 3] = bits[3];
    }
    __syncthreads();

    // Output: out[b0+bi][rb*8+ch][t]; nibble -> float4 via L1-resident LUT
#pragma unroll
    for (int i = 0; i < 4; i++) {
        int e = tid + i * NTHR;
        int r = e >> 5, t4 = e & 31;       // r = bi*8+ch
        int bi = r >> 3, ch = r & 7;
        uint32_t word = sBits[r * 4 + (t4 >> 3)];
        uint32_t nib = (word >> ((t4 & 7) * 4)) & 0xFu;
        float4 vv = __ldg(&g_lut[nib]);
        *(float4*)(out + ((size_t)(b0 + bi) * COUT + rb * 8 + ch) * TT + t4 * 4) = vv;
    }
}

// ---------------------------------------------------------------------------
// Inputs: spikes f32 [64,2048,128], weights f32 [2048,2048], mask f32
// [2048,2048], scale_exp i32 [2048], threshold_exp i32 [1].
// Output: f32 [64,2048,128].
// ---------------------------------------------------------------------------
extern "C" void kernel_launch(void* const* d_in, const int* in_sizes, int n_in,
                              void* d_out, int out_size) {
    const float* spikes    = (const float*)d_in[0];
    const float* weights   = (const float*)d_in[1];
    const float* mask      = (const float*)d_in[2];
    const int*   scale_exp = (const int*)d_in[3];
    const int*   texp      = (const int*)d_in[4];
    float*       out       = (float*)d_out;

    pack_prep_kernel<<<NRB + 8192, 256>>>(spikes, weights, mask);
    sgemm_scan_kernel<<<dim3(NRB, BB / MB), NTHR, SMEM_G>>>(scale_exp, texp, out);
}